// round 15
// baseline (speedup 1.0000x reference)
#include <cuda_runtime.h>

// CRF loss: logZ - gold.  T=512, B=512, N=64.
// Exp-space forward. ONE WARP PER CHAIN (no barriers): lane owns state
// columns 2l, 2l+1; p exchanged via smem with warp-synchronous ordering.
// 4 chains per 128-thread block (one warp per SMSP). Renorm every 6 steps
// via lagged lane-0 shfl; emit ring depth 6 with pointer-strided prefetch.

#define TT 512
#define BB 512
#define NN 64
#define LOG2E 1.4426950408889634f
#define LN2F  0.6931471805599453f
#define STRIDE_F (BB * NN)

#define FWD_BLOCKS  128                  // 4 warp-chains per 128-thread block
#define GOLD_BLOCKS 2048                 // (T*B)/128
#define TOT_BLOCKS  (FWD_BLOCKS + GOLD_BLOCKS)

typedef unsigned long long ull;

__device__ __align__(16) float g_EpT[NN * NN];   // exp(trans)^T : [j][i]
__device__ double   g_logZ;
__device__ double   g_gold;
__device__ unsigned g_done;

__device__ __forceinline__ float ex2f_(float x) {
    float y; asm("ex2.approx.ftz.f32 %0, %1;" : "=f"(y) : "f"(x)); return y;
}
__device__ __forceinline__ float lg2f_(float x) {
    float y; asm("lg2.approx.ftz.f32 %0, %1;" : "=f"(y) : "f"(x)); return y;
}
__device__ __forceinline__ void fma2_(ull& d, ull a, ull b) {
    asm("fma.rn.f32x2 %0, %1, %2, %0;" : "+l"(d) : "l"(a), "l"(b));
}
__device__ __forceinline__ ull add2_(ull a, ull b) {
    ull d; asm("add.rn.f32x2 %0, %1, %2;" : "=l"(d) : "l"(a), "l"(b));
    return d;
}
__device__ __forceinline__ float pairsum_(ull a) {
    unsigned lo, hi;
    asm("mov.b64 {%0, %1}, %2;" : "=r"(lo), "=r"(hi) : "l"(a));
    return __uint_as_float(lo) + __uint_as_float(hi);
}
__device__ __forceinline__ ull packf2_(float a, float b) {
    ull r; asm("mov.b64 %0, {%1, %2};" : "=l"(r) : "f"(a), "f"(b));
    return r;
}

// mask dtype: 0=int32, 1=float32, 2=byte  (row t=0 all-true since lengths>=1)
__device__ __forceinline__ int mask_kind(const void* maskp) {
    unsigned w0 = ((const unsigned*)maskp)[0];
    return (w0 == 1u) ? 0 : (w0 == 0x3F800000u ? 1 : 2);
}
__device__ __forceinline__ bool mask_at(const void* maskp, int kind, int idx) {
    if (kind == 0) return ((const int*)maskp)[idx] != 0;
    if (kind == 1) return ((const float*)maskp)[idx] != 0.0f;
    return ((const unsigned char*)maskp)[idx] != 0;
}

// ---------------- init ------------------------------------------------------
__global__ void k_init(const float* __restrict__ trans) {
    int tid = blockIdx.x * blockDim.x + threadIdx.x;
    if (tid < NN * NN) {
        int i = tid & (NN - 1);
        int j = tid >> 6;
        g_EpT[tid] = ex2f_(LOG2E * trans[i * NN + j]);
    }
    if (tid == 0) { g_logZ = 0.0; g_gold = 0.0; g_done = 0u; }
}

// ---------------- fused forward + gold + final ------------------------------
__global__ void __launch_bounds__(128, 1)
k_main(const float* __restrict__ emit,
       const float* __restrict__ trans,
       const float* __restrict__ strans,
       const float* __restrict__ etrans,
       const int*   __restrict__ target,
       const void*  __restrict__ maskp,
       float*       __restrict__ out) {
    __shared__ __align__(16) float pbuf[4][2][NN];  // [chain][buffer][pairs]

    const int tid = threadIdx.x;

    if (blockIdx.x < FWD_BLOCKS) {
        const int wid = tid >> 5;         // chain index within block
        const int l   = tid & 31;         // lane owns columns 2l, 2l+1
        const int b   = blockIdx.x * 4 + wid;

        // chain length from prefix mask (intra-warp only)
        const int kind = mask_kind(maskp);
        int cnt = 0;
#pragma unroll
        for (int k = 0; k < 16; ++k)
            cnt += mask_at(maskp, kind, (l + 32 * k) * BB + b) ? 1 : 0;
        const int len = __reduce_add_sync(0xffffffffu, cnt);

        // E columns 2l and 2l+1, i-pair packed: 64 x f32x2 registers
        ull EA[32], EB[32];
        {
            const ull* ea = (const ull*)(g_EpT + (2 * l) * NN);
            const ull* ebp = (const ull*)(g_EpT + (2 * l + 1) * NN);
#pragma unroll
            for (int k = 0; k < 32; ++k) { EA[k] = ea[k]; EB[k] = ebp[k]; }
        }

        const float* ebase = emit + (size_t)b * NN + 2 * l;

        float2 e0 = *(const float2*)ebase;
        float2 st = *(const float2*)(strans + 2 * l);
        float A0 = LOG2E * (e0.x + st.x);
        float A1 = LOG2E * (e0.y + st.y);
        const float M0 = __shfl_sync(0xffffffffu, A0, 0);
        float PF0 = ex2f_(A0 - M0);
        float PF1 = ex2f_(A1 - M0);
        float mlog = M0;
        float u = 1.0f;
        float sh = 1.0f;                  // lagged lane-0 raw-sum sample

        ((ull*)pbuf[wid][1])[l] = packf2_(PF0, PF1);

        // prologue: g for step 1, raw float2 ring for steps 2..7 (clamped)
#define LDPF(tt) (*(const float2*)(ebase + (size_t)((tt) < TT - 1 ? (tt) : (TT - 1)) * STRIDE_F))
        float2 rr1 = LDPF(1);
        float2 gcur = make_float2(ex2f_(LOG2E * rr1.x), ex2f_(LOG2E * rr1.y));
        float2 r0 = LDPF(2), r1 = LDPF(3), r2 = LDPF(4);
        float2 r3 = LDPF(5), r4 = LDPF(6), r5 = LDPF(7);
        const float2* pf = (const float2*)(ebase + (size_t)8 * STRIDE_F);
        __syncwarp();

        int t = 1;
        // Cadence K = 0..5.  K==4: sample lane-0 raw sum via shfl (lagged).
        // K==5: derive scale u from the sample, apply, account mlog.
#define BODY(RR, BI, BO, K) {                                                 \
        float ggx = gcur.x, ggy = gcur.y;                                     \
        if (K == 5) {                                                         \
            int ex = (int)((__float_as_uint(sh) >> 23) & 0xFF);               \
            int dd = ex - 127;                                                \
            if (ex == 0 || ex == 255) dd = 0;                                 \
            if (dd > 120) dd = 120; if (dd < -120) dd = -120;                 \
            u = __uint_as_float((unsigned)(127 - dd) << 23);                  \
            mlog += (float)dd;                                                \
            ggx *= u; ggy *= u;                                               \
        }                                                                     \
        const ulonglong2* pb = (const ulonglong2*)pbuf[wid][BI];              \
        ull aA0 = 0, aA1 = 0, aA2 = 0, aA3 = 0;                               \
        ull aB0 = 0, aB1 = 0, aB2 = 0, aB3 = 0;                               \
        _Pragma("unroll")                                                     \
        for (int m = 0; m < 16; m += 2) {                                     \
            ulonglong2 q = pb[m];                                             \
            ulonglong2 r = pb[m + 1];                                         \
            fma2_(aA0, q.x, EA[2 * m]);     fma2_(aA1, q.y, EA[2 * m + 1]);   \
            fma2_(aB0, q.x, EB[2 * m]);     fma2_(aB1, q.y, EB[2 * m + 1]);   \
            fma2_(aA2, r.x, EA[2 * m + 2]); fma2_(aA3, r.y, EA[2 * m + 3]);   \
            fma2_(aB2, r.x, EB[2 * m + 2]); fma2_(aB3, r.y, EB[2 * m + 3]);   \
        }                                                                     \
        float s0 = pairsum_(add2_(add2_(aA0, aA1), add2_(aA2, aA3)));         \
        float s1 = pairsum_(add2_(add2_(aB0, aB1), add2_(aB2, aB3)));         \
        float pn0 = s0 * ggx;                                                 \
        float pn1 = s1 * ggy;                                                 \
        ((ull*)pbuf[wid][BO])[l] = packf2_(pn0, pn1);                         \
        if (K == 4) sh = __shfl_sync(0xffffffffu, s0, 0);  /* lagged */       \
        gcur.x = ex2f_(LOG2E * RR.x);  /* shadow work */                      \
        gcur.y = ex2f_(LOG2E * RR.y);                                         \
        RR = *pf; pf += BB * NN / 2;   /* clamp-free strided prefetch */      \
        PF0 = pn0; PF1 = pn1;                                                 \
        ++t;                                                                  \
        __syncwarp(); }

        while (t + 12 < len) {            // cadence-aligned: t ≡ 1 (mod 6)
            BODY(r0, 1, 0, 0)
            BODY(r1, 0, 1, 1)
            BODY(r2, 1, 0, 2)
            BODY(r3, 0, 1, 3)
            BODY(r4, 1, 0, 4)             // sample lane-0 sum
            BODY(r5, 0, 1, 5)             // derive + apply scale
        }
        {
            const float2* er = (const float2*)(ebase + (size_t)t * STRIDE_F);
            while (t < len) {             // ≤12 remainder steps
                float2 rrv = *er; er += BB * NN / 2;
                int bi = t & 1, bo = bi ^ 1;
                float gx = ex2f_(LOG2E * rrv.x);
                float gy = ex2f_(LOG2E * rrv.y);
                const ulonglong2* pb = (const ulonglong2*)pbuf[wid][bi];
                ull aA0 = 0, aA1 = 0, aA2 = 0, aA3 = 0;
                ull aB0 = 0, aB1 = 0, aB2 = 0, aB3 = 0;
#pragma unroll
                for (int m = 0; m < 16; m += 2) {
                    ulonglong2 q = pb[m];
                    ulonglong2 r = pb[m + 1];
                    fma2_(aA0, q.x, EA[2 * m]);     fma2_(aA1, q.y, EA[2 * m + 1]);
                    fma2_(aB0, q.x, EB[2 * m]);     fma2_(aB1, q.y, EB[2 * m + 1]);
                    fma2_(aA2, r.x, EA[2 * m + 2]); fma2_(aA3, r.y, EA[2 * m + 3]);
                    fma2_(aB2, r.x, EB[2 * m + 2]); fma2_(aB3, r.y, EB[2 * m + 3]);
                }
                float s0 = pairsum_(add2_(add2_(aA0, aA1), add2_(aA2, aA3)));
                float s1 = pairsum_(add2_(add2_(aB0, aB1), add2_(aB2, aB3)));
                // exact 2^-6-per-step compensation keeps p in fp32 range
                float pn0 = s0 * (gx * 0.015625f);
                float pn1 = s1 * (gy * 0.015625f);
                ((ull*)pbuf[wid][bo])[l] = packf2_(pn0, pn1);
                mlog += 6.0f;
                PF0 = pn0; PF1 = pn1;
                ++t;
                __syncwarp();
            }
        }

        // logZ_b = ln LSE_j(alpha_j + etrans_j),  alpha(log2) = lg2(PF)+mlog
        float2 et = *(const float2*)(etrans + 2 * l);
        float G0 = lg2f_(PF0) + mlog + LOG2E * et.x;
        float G1 = lg2f_(PF1) + mlog + LOG2E * et.y;
        float m2 = fmaxf(G0, G1);
#pragma unroll
        for (int o = 16; o; o >>= 1) m2 = fmaxf(m2, __shfl_xor_sync(0xffffffffu, m2, o));
        float s = ex2f_(G0 - m2) + ex2f_(G1 - m2);
#pragma unroll
        for (int o = 16; o; o >>= 1) s += __shfl_xor_sync(0xffffffffu, s, o);
        if (l == 0)
            atomicAdd(&g_logZ, (double)(LN2F * (m2 + lg2f_(s))));
    } else {
        // ======== gold path score ========
        int idx = (blockIdx.x - FWD_BLOCKS) * 128 + tid;   // = t*BB + b
        int t = idx >> 9;
        int kind = mask_kind(maskp);
        float c = 0.0f;
        if (mask_at(maskp, kind, idx)) {
            int tg = target[idx];
            c = emit[(size_t)idx * NN + tg];
            if (t > 0) c += trans[target[idx - BB] * NN + tg];
            else       c += strans[tg];
            bool mnext = (t < TT - 1) && mask_at(maskp, kind, idx + BB);
            if (!mnext) c += etrans[tg];
        }
#pragma unroll
        for (int o = 16; o; o >>= 1) c += __shfl_xor_sync(0xffffffffu, c, o);
        if ((tid & 31) == 0) atomicAdd(&g_gold, (double)c);
    }

    // ======== last block writes the result ========
    __syncthreads();
    if (tid == 0) {
        __threadfence();
        if (atomicAdd(&g_done, 1u) == TOT_BLOCKS - 1) {
            double lz = atomicAdd(&g_logZ, 0.0);
            double gd = atomicAdd(&g_gold, 0.0);
            out[0] = (float)(lz - gd);
        }
    }
}

extern "C" void kernel_launch(void* const* d_in, const int* in_sizes, int n_in,
                              void* d_out, int out_size) {
    const float* emit   = (const float*)d_in[0];
    const float* trans  = (const float*)d_in[1];
    const float* strans = (const float*)d_in[2];
    const float* etrans = (const float*)d_in[3];
    const int*   target = (const int*)d_in[4];
    const void*  mask   = d_in[5];
    (void)in_sizes; (void)n_in; (void)out_size;

    k_init<<<16, 256>>>(trans);
    k_main<<<TOT_BLOCKS, 128>>>(emit, trans, strans, etrans, target, mask,
                                (float*)d_out);
}